// round 13
// baseline (speedup 1.0000x reference)
#include <cuda_runtime.h>
#include <cuda_bf16.h>
#include <cstdint>

// Fixed shapes
#define H_DIM   1024
#define N_DIM   64
#define SEQ_L   2048
// Per-h GEMM (J=32 split):  l = 32c + j,  c = 0..63, j = 0..31
//   A[c, 2n] = Re(Ct2 * r^(32c)),  A[c, 2n+1] = Im(...)     (64 x 128)
//   B[2n, j] = Re(r^j),            B[2n+1, j] = -Im(r^j)    (stored [j][kappa])
// bf16 split X = Xhi + Xmid; D = AhBh + AhBm + AmBh (3 independent acc chains).

// SMEM tiles: row-major, 256B rows, XOR-swizzle in 16B units by (row&7)<<4
#define A_HI_OFF   0        // 64 x 256B = 16384
#define A_MID_OFF  16384
#define B_HI_OFF   32768    // 32 x 256B = 8192
#define B_MID_OFF  40960
#define SMEM_BYTES 49152    // 48KB -> 4 CTAs/SM

__device__ __forceinline__ uint32_t smem_u32(const void* p) {
    uint32_t a;
    asm("{ .reg .u64 t; cvta.to.shared.u64 t, %1; cvt.u32.u64 %0, t; }" : "=r"(a) : "l"(p));
    return a;
}
__device__ __forceinline__ uint32_t cvt_bf16x2(float hi_f, float lo_f) {
    uint32_t r;
    asm("cvt.rn.bf16x2.f32 %0, %1, %2;" : "=r"(r) : "f"(hi_f), "f"(lo_f));
    return r;
}
// Split f32 pair into hi-bf16x2 + mid-bf16x2 (residual), store to both tiles.
__device__ __forceinline__ void split_store(char* sm, uint32_t addr,
                                            float lo, float hi, bool isA) {
    uint32_t pk = cvt_bf16x2(hi, lo);
    float lo_h = __uint_as_float(pk << 16);
    float hi_h = __uint_as_float(pk & 0xFFFF0000u);
    uint32_t pm = cvt_bf16x2(hi - hi_h, lo - lo_h);
    uint32_t oh = isA ? A_HI_OFF : B_HI_OFF;
    uint32_t om = isA ? A_MID_OFF : B_MID_OFF;
    *reinterpret_cast<uint32_t*>(sm + oh + addr) = pk;
    *reinterpret_cast<uint32_t*>(sm + om + addr) = pm;
}
__device__ __forceinline__ void ldsm4(uint32_t* r, uint32_t addr) {
    asm volatile("ldmatrix.sync.aligned.m8n8.x4.shared.b16 {%0,%1,%2,%3}, [%4];"
                 : "=r"(r[0]), "=r"(r[1]), "=r"(r[2]), "=r"(r[3]) : "r"(addr));
}
__device__ __forceinline__ void mma_bf16(float* d, const uint32_t* a,
                                         uint32_t b0, uint32_t b1) {
    asm volatile(
        "mma.sync.aligned.m16n8k16.row.col.f32.bf16.bf16.f32 "
        "{%0,%1,%2,%3}, {%4,%5,%6,%7}, {%8,%9}, {%0,%1,%2,%3};"
        : "+f"(d[0]), "+f"(d[1]), "+f"(d[2]), "+f"(d[3])
        : "r"(a[0]), "r"(a[1]), "r"(a[2]), "r"(a[3]), "r"(b0), "r"(b1));
}

__global__ void __launch_bounds__(256, 4) ssk_hmma(
    const float* __restrict__ Cri, const float* __restrict__ logdt,
    const float* __restrict__ Bri, const float* __restrict__ invAr,
    const float* __restrict__ Aim, float* __restrict__ out)
{
    extern __shared__ __align__(1024) char sm[];
    const int tx = threadIdx.x;
    const int h  = blockIdx.x;

    // ================= Generation phase =================
    {
        const int n  = tx & 63;
        const int q4 = tx >> 6;                      // quarter 0..3
        const int idx = h * N_DIM + n;

        float cr = Cri[2 * idx], ci = Cri[2 * idx + 1];
        float br = Bri[2 * idx], bi = Bri[2 * idx + 1];
        float dt = __expf(logdt[h]);
        float Ar = -__expf(invAr[idx]);
        float Ai = Aim[idx];

        float zr = Ar * dt, zi = Ai * dt;
        float dr = 1.0f - 0.5f * zr, di = -0.5f * zi;
        float inv = 1.0f / (dr * dr + di * di);

        float bcr = br * cr - bi * ci;
        float bci = br * ci + bi * cr;
        float s = 2.0f * dt * inv;
        float ctr = (bcr * dr + bci * di) * s;       // Ct2 = 2*B*C*dt/den
        float cti = (bci * dr - bcr * di) * s;

        float nr = 1.0f + 0.5f * zr, ni = 0.5f * zi;
        float rr = (nr * dr + ni * di) * inv;        // r, |r| < 1
        float ri = (ni * dr - nr * di) * inv;

        // powers r^2, r^4, r^8, r^16, r^32 (= rho), rho^2
        float r2r  = rr * rr - ri * ri,      r2i  = 2.0f * rr * ri;
        float r4r  = r2r * r2r - r2i * r2i,  r4i  = 2.0f * r2r * r2i;
        float r8r  = r4r * r4r - r4i * r4i,  r8i  = 2.0f * r4r * r4i;
        float r16r = r8r * r8r - r8i * r8i,  r16i = 2.0f * r8r * r8i;
        float pr   = r16r * r16r - r16i * r16i, pi = 2.0f * r16r * r16i;  // rho
        float p2r  = pr * pr - pi * pi,      p2i  = 2.0f * pr * pi;       // rho^2

        const uint32_t colb = (uint32_t)n * 4u;

        // ---- B rows j = 8*q4 .. +7 : (Re r^j, -Im r^j), 2 chains (r^2) ----
        {
            float er = 1.0f, ei = 0.0f;
            if (q4 & 1) { er = r8r; ei = r8i; }
            if (q4 & 2) {                            // *= r^16
                float t = er * r16r - ei * r16i;
                ei = er * r16i + ei * r16r;
                er = t;
            }
            float orr = er * rr - ei * ri;           // odd chain = even * r
            float ori = er * ri + ei * rr;
            const uint32_t jb = (uint32_t)(8 * q4) * 256u;
#pragma unroll
            for (int i = 0; i < 8; i += 2) {
                uint32_t ae = jb + (uint32_t)i * 256u + (colb ^ ((uint32_t)i << 4));
                uint32_t ao = jb + (uint32_t)(i + 1) * 256u
                            + (colb ^ ((uint32_t)(i + 1) << 4));
                split_store(sm, ae, er, -ei, false);
                split_store(sm, ao, orr, -ori, false);
                float t = er * r2r - ei * r2i;       // even *= r^2
                ei = er * r2i + ei * r2r;
                er = t;
                t = orr * r2r - ori * r2i;           // odd  *= r^2
                ori = orr * r2i + ori * r2r;
                orr = t;
            }
        }

        // ---- A rows c = 16*q4 .. +15 : W = Ct2 * rho^c, 2 chains (rho^2) ----
        float wr = ctr, wi = cti;
        {
            float s16r = pr, s16i = pi;              // rho^16 via 4 squarings
#pragma unroll
            for (int i = 0; i < 4; i++) {
                float t = s16r * s16r - s16i * s16i;
                s16i = 2.0f * s16r * s16i;
                s16r = t;
            }
            float mr = 1.0f, mi = 0.0f;
            if (q4 & 1) { mr = s16r; mi = s16i; }
            if (q4 & 2) {
                float s32r = s16r * s16r - s16i * s16i;
                float s32i = 2.0f * s16r * s16i;
                float t = mr * s32r - mi * s32i;
                mi = mr * s32i + mi * s32r;
                mr = t;
            }
            float t = wr * mr - wi * mi;
            wi = wr * mi + wi * mr;
            wr = t;
        }
        float vr = wr * pr - wi * pi;                // odd chain = w * rho
        float vi = wr * pi + wi * pr;
        const uint32_t cb = (uint32_t)(16 * q4) * 256u;
#pragma unroll
        for (int i = 0; i < 16; i += 2) {
            uint32_t ae = cb + (uint32_t)i * 256u
                        + (colb ^ (((uint32_t)(i & 7)) << 4));
            uint32_t ao = cb + (uint32_t)(i + 1) * 256u
                        + (colb ^ (((uint32_t)((i + 1) & 7)) << 4));
            split_store(sm, ae, wr, wi, true);
            split_store(sm, ao, vr, vi, true);
            float t = wr * p2r - wi * p2i;           // even *= rho^2
            wi = wr * p2i + wi * p2r;
            wr = t;
            t = vr * p2r - vi * p2i;                 // odd  *= rho^2
            vi = vr * p2i + vi * p2r;
            vr = t;
        }
    }
    __syncthreads();

    // ====== MMA phase: 8 warps = (mt 0..3) x (nh 0..1), m16 x n16 each ======
    const int wid = tx >> 5;
    const int lid = tx & 31;
    const int mt  = wid & 3;
    const int nh  = wid >> 2;

    // 6 independent accumulator chains: {hh, hm, mh} x {nt0, nt1}
    float dhh[2][4], dhm[2][4], dmh[2][4];
#pragma unroll
    for (int nt = 0; nt < 2; nt++)
#pragma unroll
        for (int i = 0; i < 4; i++) { dhh[nt][i] = 0.f; dhm[nt][i] = 0.f; dmh[nt][i] = 0.f; }

    const uint32_t lrow = (uint32_t)(lid & 15);
    const uint32_t c16  = (uint32_t)(lid & 16);      // k-half select (16B)
    const uint32_t swz  = (lrow & 7u) << 4;
    const uint32_t sbase = smem_u32(sm);
    const uint32_t a_rowb = sbase + ((uint32_t)(mt * 16) + lrow) * 256u;
    const uint32_t b_rowb = sbase + ((uint32_t)(nh * 16) + lrow) * 256u;

    // precompute per-kt swizzled column offsets (one reg each)
    uint32_t kcol[8];
#pragma unroll
    for (int kt = 0; kt < 8; kt++)
        kcol[kt] = ((uint32_t)(kt * 32) + c16) ^ swz;

#pragma unroll
    for (int kt = 0; kt < 8; kt++) {
        uint32_t a_hi[4], a_md[4], bh[4], bm[4];
        ldsm4(a_hi, a_rowb + A_HI_OFF  + kcol[kt]);
        ldsm4(bh,   b_rowb + B_HI_OFF  + kcol[kt]);  // m0/m1: nt0/nt1 (k lo), m2/m3: (k hi)
        ldsm4(a_md, a_rowb + A_MID_OFF + kcol[kt]);
        ldsm4(bm,   b_rowb + B_MID_OFF + kcol[kt]);

        mma_bf16(dhh[0], a_hi, bh[0], bh[2]);
        mma_bf16(dhh[1], a_hi, bh[1], bh[3]);
        mma_bf16(dhm[0], a_hi, bm[0], bm[2]);
        mma_bf16(dhm[1], a_hi, bm[1], bm[3]);
        mma_bf16(dmh[0], a_md, bh[0], bh[2]);
        mma_bf16(dmh[1], a_md, bh[1], bh[3]);
    }

    // ================= Epilogue: D[c, j] -> out[h, 32c + j] =================
    float* outh = out + (size_t)h * SEQ_L;
    const int row = mt * 16 + (lid >> 2);            // c index (and row+8)
    const int jb  = nh * 16 + 2 * (lid & 3);         // j base
#pragma unroll
    for (int nt = 0; nt < 2; nt++) {
        float s0 = dhh[nt][0] + dhm[nt][0] + dmh[nt][0];
        float s1 = dhh[nt][1] + dhm[nt][1] + dmh[nt][1];
        float s2 = dhh[nt][2] + dhm[nt][2] + dmh[nt][2];
        float s3 = dhh[nt][3] + dhm[nt][3] + dmh[nt][3];
        *reinterpret_cast<float2*>(outh + 32 * row + jb + 8 * nt) = make_float2(s0, s1);
        *reinterpret_cast<float2*>(outh + 32 * (row + 8) + jb + 8 * nt) = make_float2(s2, s3);
    }
}

extern "C" void kernel_launch(void* const* d_in, const int* in_sizes, int n_in,
                              void* d_out, int out_size)
{
    const float* Cri   = (const float*)d_in[0];   // (1, H, N, 2)
    const float* logdt = (const float*)d_in[1];   // (H,)
    const float* Bri   = (const float*)d_in[2];   // (H, N, 2)  (n_ssm == H)
    const float* invAr = (const float*)d_in[3];   // (H, N)
    const float* Aim   = (const float*)d_in[4];   // (H, N)
    float* out = (float*)d_out;                   // (1, H, L)

    cudaFuncSetAttribute(ssk_hmma, cudaFuncAttributeMaxDynamicSharedMemorySize,
                         SMEM_BYTES);
    ssk_hmma<<<H_DIM, 256, SMEM_BYTES>>>(Cri, logdt, Bri, invAr, Aim, out);
}

// round 14
// speedup vs baseline: 1.1860x; 1.1860x over previous
#include <cuda_runtime.h>
#include <cuda_bf16.h>
#include <cstdint>

// Fixed shapes
#define H_DIM   1024
#define N_DIM   64
#define SEQ_L   2048
// Per-h GEMM (J=32 split):  l = 32c + j,  c = 0..63, j = 0..31
//   D[c, j] = sum_kappa A[c, kappa] * B[kappa, j]
//   A[c, 2n] = Re(Ct2 * r^(32c)),  A[c, 2n+1] = Im(...)     (64 x 128) fp16
//   B[2n, j] = Re(r^j),            B[2n+1, j] = -Im(r^j)    (stored [j][kappa]) fp16
// Single-pass fp16 MMA (m16n8k16), f32 accumulate. Per-term err ~2^-10 -> ~1e-4.

// SMEM: row-major, 256B rows, XOR-swizzle in 16B units by (row&7)<<4
#define A_OFF      0        // 64 x 256B = 16384
#define B_OFF      16384    // 32 x 256B = 8192
#define SMEM_BYTES 24576    // 24KB

__device__ __forceinline__ uint32_t smem_u32(const void* p) {
    uint32_t a;
    asm("{ .reg .u64 t; cvta.to.shared.u64 t, %1; cvt.u32.u64 %0, t; }" : "=r"(a) : "l"(p));
    return a;
}
__device__ __forceinline__ uint32_t cvt_f16x2(float hi_f, float lo_f) {
    uint32_t r;
    asm("cvt.rn.f16x2.f32 %0, %1, %2;" : "=r"(r) : "f"(hi_f), "f"(lo_f));
    return r;
}
__device__ __forceinline__ void ldsm4(uint32_t* r, uint32_t addr) {
    asm volatile("ldmatrix.sync.aligned.m8n8.x4.shared.b16 {%0,%1,%2,%3}, [%4];"
                 : "=r"(r[0]), "=r"(r[1]), "=r"(r[2]), "=r"(r[3]) : "r"(addr));
}
__device__ __forceinline__ void mma_f16(float* d, const uint32_t* a,
                                        uint32_t b0, uint32_t b1) {
    asm volatile(
        "mma.sync.aligned.m16n8k16.row.col.f32.f16.f16.f32 "
        "{%0,%1,%2,%3}, {%4,%5,%6,%7}, {%8,%9}, {%0,%1,%2,%3};"
        : "+f"(d[0]), "+f"(d[1]), "+f"(d[2]), "+f"(d[3])
        : "r"(a[0]), "r"(a[1]), "r"(a[2]), "r"(a[3]), "r"(b0), "r"(b1));
}

__global__ void __launch_bounds__(256) ssk_hmma(
    const float* __restrict__ Cri, const float* __restrict__ logdt,
    const float* __restrict__ Bri, const float* __restrict__ invAr,
    const float* __restrict__ Aim, float* __restrict__ out)
{
    extern __shared__ __align__(1024) char sm[];
    const int tx = threadIdx.x;
    const int h  = blockIdx.x;

    // ================= Generation phase =================
    {
        const int n  = tx & 63;
        const int q4 = tx >> 6;                      // quarter 0..3
        const int idx = h * N_DIM + n;

        float cr = Cri[2 * idx], ci = Cri[2 * idx + 1];
        float br = Bri[2 * idx], bi = Bri[2 * idx + 1];
        float dt = __expf(logdt[h]);
        float Ar = -__expf(invAr[idx]);
        float Ai = Aim[idx];

        float zr = Ar * dt, zi = Ai * dt;
        float dr = 1.0f - 0.5f * zr, di = -0.5f * zi;
        float inv = 1.0f / (dr * dr + di * di);

        float bcr = br * cr - bi * ci;
        float bci = br * ci + bi * cr;
        float s = 2.0f * dt * inv;
        float ctr = (bcr * dr + bci * di) * s;       // Ct2 = 2*B*C*dt/den
        float cti = (bci * dr - bcr * di) * s;

        float nr = 1.0f + 0.5f * zr, ni = 0.5f * zi;
        float rr = (nr * dr + ni * di) * inv;        // r, |r| < 1
        float ri = (ni * dr - nr * di) * inv;

        // powers r^2, r^4, r^8, r^16, r^32 (= rho), rho^2
        float r2r  = rr * rr - ri * ri,      r2i  = 2.0f * rr * ri;
        float r4r  = r2r * r2r - r2i * r2i,  r4i  = 2.0f * r2r * r2i;
        float r8r  = r4r * r4r - r4i * r4i,  r8i  = 2.0f * r4r * r4i;
        float r16r = r8r * r8r - r8i * r8i,  r16i = 2.0f * r8r * r8i;
        float pr   = r16r * r16r - r16i * r16i, pi = 2.0f * r16r * r16i;  // rho
        float p2r  = pr * pr - pi * pi,      p2i  = 2.0f * pr * pi;       // rho^2

        const uint32_t colb = (uint32_t)n * 4u;

        // ---- B rows j = 8*q4 .. +7 : (Re r^j, -Im r^j), 2 chains (r^2) ----
        {
            float er = 1.0f, ei = 0.0f;
            if (q4 & 1) { er = r8r; ei = r8i; }
            if (q4 & 2) {                            // *= r^16
                float t = er * r16r - ei * r16i;
                ei = er * r16i + ei * r16r;
                er = t;
            }
            float orr = er * rr - ei * ri;           // odd chain = even * r
            float ori = er * ri + ei * rr;
            const uint32_t jb = (uint32_t)(8 * q4) * 256u;
#pragma unroll
            for (int i = 0; i < 8; i += 2) {
                uint32_t ae = jb + (uint32_t)i * 256u + (colb ^ ((uint32_t)i << 4));
                uint32_t ao = jb + (uint32_t)(i + 1) * 256u
                            + (colb ^ ((uint32_t)(i + 1) << 4));
                *reinterpret_cast<uint32_t*>(sm + B_OFF + ae) = cvt_f16x2(-ei, er);
                *reinterpret_cast<uint32_t*>(sm + B_OFF + ao) = cvt_f16x2(-ori, orr);
                float t = er * r2r - ei * r2i;       // even *= r^2
                ei = er * r2i + ei * r2r;
                er = t;
                t = orr * r2r - ori * r2i;           // odd  *= r^2
                ori = orr * r2i + ori * r2r;
                orr = t;
            }
        }

        // ---- A rows c = 16*q4 .. +15 : W = Ct2 * rho^c, 2 chains (rho^2) ----
        float wr = ctr, wi = cti;
        {
            float s16r = pr, s16i = pi;              // rho^16 via 4 squarings
#pragma unroll
            for (int i = 0; i < 4; i++) {
                float t = s16r * s16r - s16i * s16i;
                s16i = 2.0f * s16r * s16i;
                s16r = t;
            }
            float mr = 1.0f, mi = 0.0f;
            if (q4 & 1) { mr = s16r; mi = s16i; }
            if (q4 & 2) {
                float s32r = s16r * s16r - s16i * s16i;
                float s32i = 2.0f * s16r * s16i;
                float t = mr * s32r - mi * s32i;
                mi = mr * s32i + mi * s32r;
                mr = t;
            }
            float t = wr * mr - wi * mi;
            wi = wr * mi + wi * mr;
            wr = t;
        }
        float vr = wr * pr - wi * pi;                // odd chain = w * rho
        float vi = wr * pi + wi * pr;
        const uint32_t cb = (uint32_t)(16 * q4) * 256u;
#pragma unroll
        for (int i = 0; i < 16; i += 2) {
            uint32_t ae = cb + (uint32_t)i * 256u
                        + (colb ^ (((uint32_t)(i & 7)) << 4));
            uint32_t ao = cb + (uint32_t)(i + 1) * 256u
                        + (colb ^ (((uint32_t)((i + 1) & 7)) << 4));
            *reinterpret_cast<uint32_t*>(sm + A_OFF + ae) = cvt_f16x2(wi, wr);
            *reinterpret_cast<uint32_t*>(sm + A_OFF + ao) = cvt_f16x2(vi, vr);
            float t = wr * p2r - wi * p2i;           // even *= rho^2
            wi = wr * p2i + wi * p2r;
            wr = t;
            t = vr * p2r - vi * p2i;                 // odd  *= rho^2
            vi = vr * p2i + vi * p2r;
            vr = t;
        }
    }
    __syncthreads();

    // ====== MMA phase: 8 warps = (mt 0..3) x (nh 0..1), m16 x n16 each ======
    const int wid = tx >> 5;
    const int lid = tx & 31;
    const int mt  = wid & 3;
    const int nh  = wid >> 2;

    float d[2][4];
#pragma unroll
    for (int nt = 0; nt < 2; nt++)
#pragma unroll
        for (int i = 0; i < 4; i++) d[nt][i] = 0.0f;

    const uint32_t lrow = (uint32_t)(lid & 15);
    const uint32_t c16  = (uint32_t)(lid & 16);      // k-half select (16B)
    const uint32_t swz  = (lrow & 7u) << 4;
    const uint32_t sbase = smem_u32(sm);
    const uint32_t a_rowb = sbase + A_OFF + ((uint32_t)(mt * 16) + lrow) * 256u;
    const uint32_t b_rowb = sbase + B_OFF + ((uint32_t)(nh * 16) + lrow) * 256u;

    uint32_t kcol[8];
#pragma unroll
    for (int kt = 0; kt < 8; kt++)
        kcol[kt] = ((uint32_t)(kt * 32) + c16) ^ swz;

#pragma unroll
    for (int kt = 0; kt < 8; kt++) {
        uint32_t a[4], b[4];
        ldsm4(a, a_rowb + kcol[kt]);
        ldsm4(b, b_rowb + kcol[kt]);   // m0/m1: nt0/nt1 (k lo), m2/m3: (k hi)
        mma_f16(d[0], a, b[0], b[2]);
        mma_f16(d[1], a, b[1], b[3]);
    }

    // ================= Epilogue: D[c, j] -> out[h, 32c + j] =================
    float* outh = out + (size_t)h * SEQ_L;
    const int row = mt * 16 + (lid >> 2);            // c index (and row+8)
    const int jb  = nh * 16 + 2 * (lid & 3);         // j base
#pragma unroll
    for (int nt = 0; nt < 2; nt++) {
        *reinterpret_cast<float2*>(outh + 32 * row + jb + 8 * nt) =
            make_float2(d[nt][0], d[nt][1]);
        *reinterpret_cast<float2*>(outh + 32 * (row + 8) + jb + 8 * nt) =
            make_float2(d[nt][2], d[nt][3]);
    }
}

extern "C" void kernel_launch(void* const* d_in, const int* in_sizes, int n_in,
                              void* d_out, int out_size)
{
    const float* Cri   = (const float*)d_in[0];   // (1, H, N, 2)
    const float* logdt = (const float*)d_in[1];   // (H,)
    const float* Bri   = (const float*)d_in[2];   // (H, N, 2)  (n_ssm == H)
    const float* invAr = (const float*)d_in[3];   // (H, N)
    const float* Aim   = (const float*)d_in[4];   // (H, N)
    float* out = (float*)d_out;                   // (1, H, L)

    cudaFuncSetAttribute(ssk_hmma, cudaFuncAttributeMaxDynamicSharedMemorySize,
                         SMEM_BYTES);
    ssk_hmma<<<H_DIM, 256, SMEM_BYTES>>>(Cri, logdt, Bri, invAr, Aim, out);
}

// round 15
// speedup vs baseline: 1.2179x; 1.0269x over previous
#include <cuda_runtime.h>
#include <cuda_bf16.h>
#include <cstdint>

// Fixed shapes
#define H_DIM   1024
#define N_DIM   64
#define SEQ_L   2048
// Per-h GEMM (J=32 split):  l = 32c + j,  c = 0..63, j = 0..31
//   A[c, 2n] = Re(Ct2 * r^(32c)),  A[c, 2n+1] = Im(...)     (64 x 128) fp16
//   B[2n, j] = Re(r^j),            B[2n+1, j] = -Im(r^j)    (stored [j][kappa]) fp16
// Single-pass fp16 MMA (m16n8k16), f32 accumulate.

// SMEM: A/B tiles row-major 256B rows, XOR-swizzle in 16B units by (row&7)<<4.
#define A_OFF      0        // 64 x 256B = 16384
#define B_OFF      16384    // 32 x 256B = 8192
#define P_OFF      24576    // 9 param arrays x 64 float2 = 4608
#define P_CT       (P_OFF + 0)
#define P_R        (P_OFF + 512)
#define P_R4       (P_OFF + 1024)
#define P_R8       (P_OFF + 1536)
#define P_R16      (P_OFF + 2048)
#define P_RHO      (P_OFF + 2560)
#define P_RHO8     (P_OFF + 3072)
#define P_RHO16    (P_OFF + 3584)
#define P_RHO32    (P_OFF + 4096)
#define SMEM_BYTES (24576 + 4608)

__device__ __forceinline__ uint32_t smem_u32(const void* p) {
    uint32_t a;
    asm("{ .reg .u64 t; cvta.to.shared.u64 t, %1; cvt.u32.u64 %0, t; }" : "=r"(a) : "l"(p));
    return a;
}
__device__ __forceinline__ uint32_t cvt_f16x2(float hi_f, float lo_f) {
    uint32_t r;
    asm("cvt.rn.f16x2.f32 %0, %1, %2;" : "=r"(r) : "f"(hi_f), "f"(lo_f));
    return r;
}
__device__ __forceinline__ float2 cmul(float2 a, float2 b) {
    return make_float2(a.x * b.x - a.y * b.y, a.x * b.y + a.y * b.x);
}
__device__ __forceinline__ float2 csqr(float2 a) {
    return make_float2(a.x * a.x - a.y * a.y, 2.0f * a.x * a.y);
}
__device__ __forceinline__ void ldsm4(uint32_t* r, uint32_t addr) {
    asm volatile("ldmatrix.sync.aligned.m8n8.x4.shared.b16 {%0,%1,%2,%3}, [%4];"
                 : "=r"(r[0]), "=r"(r[1]), "=r"(r[2]), "=r"(r[3]) : "r"(addr));
}
__device__ __forceinline__ void mma_f16(float* d, const uint32_t* a,
                                        uint32_t b0, uint32_t b1) {
    asm volatile(
        "mma.sync.aligned.m16n8k16.row.col.f32.f16.f16.f32 "
        "{%0,%1,%2,%3}, {%4,%5,%6,%7}, {%8,%9}, {%0,%1,%2,%3};"
        : "+f"(d[0]), "+f"(d[1]), "+f"(d[2]), "+f"(d[3])
        : "r"(a[0]), "r"(a[1]), "r"(a[2]), "r"(a[3]), "r"(b0), "r"(b1));
}
__device__ __forceinline__ void sts64(uint32_t addr, uint32_t w0, uint32_t w1) {
    asm volatile("st.shared.v2.b32 [%0], {%1, %2};" :: "r"(addr), "r"(w0), "r"(w1)
                 : "memory");
}

__global__ void __launch_bounds__(256) ssk_hmma(
    const float* __restrict__ Cri, const float* __restrict__ logdt,
    const float* __restrict__ Bri, const float* __restrict__ invAr,
    const float* __restrict__ Aim, float* __restrict__ out)
{
    extern __shared__ __align__(1024) char sm[];
    const int tx = threadIdx.x;
    const int h  = blockIdx.x;
    const uint32_t sbase = smem_u32(sm);

    // ========== Phase 0: per-n params (64 threads, deduped) ==========
    if (tx < 64) {
        const int n   = tx;
        const int idx = h * N_DIM + n;

        float cr = Cri[2 * idx], ci = Cri[2 * idx + 1];
        float br = Bri[2 * idx], bi = Bri[2 * idx + 1];
        float dt = __expf(logdt[h]);
        float Ar = -__expf(invAr[idx]);
        float Ai = Aim[idx];

        float zr = Ar * dt, zi = Ai * dt;
        float dr = 1.0f - 0.5f * zr, di = -0.5f * zi;
        float inv = __fdividef(1.0f, dr * dr + di * di);

        float bcr = br * cr - bi * ci;
        float bci = br * ci + bi * cr;
        float s = 2.0f * dt * inv;
        float2 ct = make_float2((bcr * dr + bci * di) * s,    // Ct2 = 2*B*C*dt/den
                                (bci * dr - bcr * di) * s);

        float nr = 1.0f + 0.5f * zr, ni = 0.5f * zi;
        float2 r = make_float2((nr * dr + ni * di) * inv,     // r, |r| < 1
                               (ni * dr - nr * di) * inv);

        float2 r2    = csqr(r);
        float2 r4    = csqr(r2);
        float2 r8    = csqr(r4);
        float2 r16   = csqr(r8);
        float2 rho   = csqr(r16);     // r^32
        float2 t64   = csqr(rho);
        float2 t128  = csqr(t64);
        float2 rho8  = csqr(t128);    // r^256
        float2 rho16 = csqr(rho8);    // r^512
        float2 rho32 = csqr(rho16);   // r^1024

        float2* P = (float2*)sm;
        ((float2*)(sm + P_CT))[n]    = ct;
        ((float2*)(sm + P_R))[n]     = r;
        ((float2*)(sm + P_R4))[n]    = r4;
        ((float2*)(sm + P_R8))[n]    = r8;
        ((float2*)(sm + P_R16))[n]   = r16;
        ((float2*)(sm + P_RHO))[n]   = rho;
        ((float2*)(sm + P_RHO8))[n]  = rho8;
        ((float2*)(sm + P_RHO16))[n] = rho16;
        ((float2*)(sm + P_RHO32))[n] = rho32;
        (void)P;
    }
    __syncthreads();

    // ========== Phase 1: tile generation (256 threads = 32 n-pairs x 8 q) ====
    {
        const int np = tx & 31;                 // n pair: n0 = 2np, n1 = 2np+1
        const int q8 = tx >> 5;                 // row group 0..7
        const uint32_t pb = (uint32_t)np * 16u; // byte offset of float2 pair

        float4 ctv    = *(const float4*)(sm + P_CT    + pb);
        float4 rv     = *(const float4*)(sm + P_R     + pb);
        float4 r4v    = *(const float4*)(sm + P_R4    + pb);
        float4 r8v    = *(const float4*)(sm + P_R8    + pb);
        float4 r16v   = *(const float4*)(sm + P_R16   + pb);
        float4 rhov   = *(const float4*)(sm + P_RHO   + pb);
        float4 rho8v  = *(const float4*)(sm + P_RHO8  + pb);
        float4 rho16v = *(const float4*)(sm + P_RHO16 + pb);
        float4 rho32v = *(const float4*)(sm + P_RHO32 + pb);

        const float2 r0   = make_float2(rv.x, rv.y),     r1   = make_float2(rv.z, rv.w);
        const float2 rho0 = make_float2(rhov.x, rhov.y), rho1 = make_float2(rhov.z, rhov.w);
        const uint32_t colb = (uint32_t)np * 8u;

        // ---- B rows j = 4*q8 .. +3 : (Re r^j, -Im r^j) ----
        {
            float2 v0 = make_float2(1.0f, 0.0f), v1 = v0;
            if (q8 & 1) { v0 = make_float2(r4v.x, r4v.y);  v1 = make_float2(r4v.z, r4v.w); }
            if (q8 & 2) { v0 = cmul(v0, make_float2(r8v.x, r8v.y));
                          v1 = cmul(v1, make_float2(r8v.z, r8v.w)); }
            if (q8 & 4) { v0 = cmul(v0, make_float2(r16v.x, r16v.y));
                          v1 = cmul(v1, make_float2(r16v.z, r16v.w)); }
#pragma unroll
            for (int i = 0; i < 4; i++) {
                int j = 4 * q8 + i;
                uint32_t addr = sbase + B_OFF + (uint32_t)j * 256u
                              + (colb ^ (((uint32_t)(j & 7)) << 4));
                sts64(addr, cvt_f16x2(-v0.y, v0.x), cvt_f16x2(-v1.y, v1.x));
                v0 = cmul(v0, r0);
                v1 = cmul(v1, r1);
            }
        }

        // ---- A rows c = 8*q8 .. +7 : W = Ct2 * rho^c ----
        {
            float2 w0 = make_float2(1.0f, 0.0f), w1 = w0;
            if (q8 & 1) { w0 = make_float2(rho8v.x, rho8v.y);
                          w1 = make_float2(rho8v.z, rho8v.w); }
            if (q8 & 2) { w0 = cmul(w0, make_float2(rho16v.x, rho16v.y));
                          w1 = cmul(w1, make_float2(rho16v.z, rho16v.w)); }
            if (q8 & 4) { w0 = cmul(w0, make_float2(rho32v.x, rho32v.y));
                          w1 = cmul(w1, make_float2(rho32v.z, rho32v.w)); }
            w0 = cmul(w0, make_float2(ctv.x, ctv.y));
            w1 = cmul(w1, make_float2(ctv.z, ctv.w));
#pragma unroll
            for (int i = 0; i < 8; i++) {
                int c = 8 * q8 + i;
                uint32_t addr = sbase + A_OFF + (uint32_t)c * 256u
                              + (colb ^ (((uint32_t)i) << 4));     // c&7 == i
                sts64(addr, cvt_f16x2(w0.y, w0.x), cvt_f16x2(w1.y, w1.x));
                w0 = cmul(w0, rho0);
                w1 = cmul(w1, rho1);
            }
        }
    }
    __syncthreads();

    // ====== MMA phase: 8 warps = (mt 0..3) x (nh 0..1), m16 x n16 each ======
    const int wid = tx >> 5;
    const int lid = tx & 31;
    const int mt  = wid & 3;
    const int nh  = wid >> 2;

    float d[2][4];
#pragma unroll
    for (int nt = 0; nt < 2; nt++)
#pragma unroll
        for (int i = 0; i < 4; i++) d[nt][i] = 0.0f;

    const uint32_t lrow = (uint32_t)(lid & 15);
    const uint32_t c16  = (uint32_t)(lid & 16);      // k-half select (16B)
    const uint32_t swz  = (lrow & 7u) << 4;
    const uint32_t a_rowb = sbase + A_OFF + ((uint32_t)(mt * 16) + lrow) * 256u;
    const uint32_t b_rowb = sbase + B_OFF + ((uint32_t)(nh * 16) + lrow) * 256u;

#pragma unroll
    for (int kt = 0; kt < 8; kt++) {
        const uint32_t col = ((uint32_t)(kt * 32) + c16) ^ swz;
        uint32_t a[4], b[4];
        ldsm4(a, a_rowb + col);
        ldsm4(b, b_rowb + col);        // m0/m1: nt0/nt1 (k lo), m2/m3: (k hi)
        mma_f16(d[0], a, b[0], b[2]);
        mma_f16(d[1], a, b[1], b[3]);
    }

    // ================= Epilogue: D[c, j] -> out[h, 32c + j] =================
    float* outh = out + (size_t)h * SEQ_L;
    const int row = mt * 16 + (lid >> 2);            // c index (and row+8)
    const int jb  = nh * 16 + 2 * (lid & 3);         // j base
#pragma unroll
    for (int nt = 0; nt < 2; nt++) {
        *reinterpret_cast<float2*>(outh + 32 * row + jb + 8 * nt) =
            make_float2(d[nt][0], d[nt][1]);
        *reinterpret_cast<float2*>(outh + 32 * (row + 8) + jb + 8 * nt) =
            make_float2(d[nt][2], d[nt][3]);
    }
}

extern "C" void kernel_launch(void* const* d_in, const int* in_sizes, int n_in,
                              void* d_out, int out_size)
{
    const float* Cri   = (const float*)d_in[0];   // (1, H, N, 2)
    const float* logdt = (const float*)d_in[1];   // (H,)
    const float* Bri   = (const float*)d_in[2];   // (H, N, 2)  (n_ssm == H)
    const float* invAr = (const float*)d_in[3];   // (H, N)
    const float* Aim   = (const float*)d_in[4];   // (H, N)
    float* out = (float*)d_out;                   // (1, H, L)

    cudaFuncSetAttribute(ssk_hmma, cudaFuncAttributeMaxDynamicSharedMemorySize,
                         SMEM_BYTES);
    ssk_hmma<<<H_DIM, 256, SMEM_BYTES>>>(Cri, logdt, Bri, invAr, Aim, out);
}